// round 17
// baseline (speedup 1.0000x reference)
#include <cuda_runtime.h>
#include <cuda_fp16.h>
#include <math.h>
#include <stdint.h>

// Problem constants
#define BSZ 2
#define SEQ 2048
#define DIM 2048
#define NH 16
#define NKV 8
#define HD 128
#define QKVD 4096          // (16 + 2*8) * 128
#define NTOK (BSZ*SEQ)     // 4096

// ---------------- scratch (static __device__, no allocations) ----------------
static __device__ __half g_q  [(size_t)BSZ * NH  * SEQ * HD];        // 16 MB
static __device__ __half g_k  [(size_t)BSZ * NKV * SEQ * HD];        // 8 MB
static __device__ __half g_v  [(size_t)BSZ * NKV * SEQ * HD];        // 8 MB (K-major)
static __device__ __half g_att[(size_t)NTOK * DIM];                  // 16 MB
static __device__ __half g_xh [(size_t)NTOK * DIM];                  // 16 MB
static __device__ __half g_wq [(size_t)QKVD * DIM];                  // 16 MB
static __device__ __half g_wo [(size_t)DIM * DIM];                   // 8 MB

__device__ __forceinline__ uint32_t smem_u32(const void* p) {
    uint32_t a;
    asm("{ .reg .u64 t; cvta.to.shared.u64 t, %1; cvt.u32.u64 %0, t; }" : "=r"(a) : "l"(p));
    return a;
}

__device__ __forceinline__ void cpa16(uint32_t saddr, const void* g) {
    asm volatile("cp.async.cg.shared.global [%0], [%1], 16;" :: "r"(saddr), "l"(g));
}

__device__ __forceinline__ float ex2f(float x) {
    float y;
    asm("ex2.approx.f32 %0, %1;" : "=f"(y) : "f"(x));
    return y;
}

#define MMA16816(acc, a0, a1, a2, a3, b0, b1) \
    asm volatile( \
        "mma.sync.aligned.m16n8k16.row.col.f32.f16.f16.f32 " \
        "{%0,%1,%2,%3}, {%4,%5,%6,%7}, {%8,%9}, {%0,%1,%2,%3};" \
        : "+f"((acc)[0]), "+f"((acc)[1]), "+f"((acc)[2]), "+f"((acc)[3]) \
        : "r"(a0), "r"(a1), "r"(a2), "r"(a3), "r"(b0), "r"(b1))

#define LDMX4(d, addr) \
    asm volatile("ldmatrix.sync.aligned.m8n8.x4.shared.b16 {%0,%1,%2,%3}, [%4];" \
        : "=r"((d)[0]), "=r"((d)[1]), "=r"((d)[2]), "=r"((d)[3]) : "r"(addr))

#define LDMX4T(d, addr) \
    asm volatile("ldmatrix.sync.aligned.m8n8.x4.trans.shared.b16 {%0,%1,%2,%3}, [%4];" \
        : "=r"((d)[0]), "=r"((d)[1]), "=r"((d)[2]), "=r"((d)[3]) : "r"(addr))

// ============================================================================
//          projection GEMM: C = A @ B^T   (K chunk 64, 2 stages)
// ============================================================================
#define GRB 144                               // row bytes: 64 halves + 16B pad
#define GSTAGE_BYTES (256 * GRB)              // 36864
#define GB_OFF (128 * GRB)                    // 18432
#define GSTAGES 2
#define GSMEM_TOTAL (GSTAGES * GSTAGE_BYTES)  // 73728 B

#define EPI_PLAIN 0
#define EPI_QKV   1

template<int EPI>
__global__ __launch_bounds__(128, 3)
void mma_gemm(const __half* __restrict__ A, const __half* __restrict__ B, float* __restrict__ C,
              int K, int lda, int ldb, int ldc,
              const float* __restrict__ cosb, const float* __restrict__ sinb,
              const float* __restrict__ qw, const float* __restrict__ kw,
              __half* __restrict__ qo, __half* __restrict__ ko, __half* __restrict__ vo)
{
    extern __shared__ char smc[];
    uint32_t sbase = smem_u32(smc);

    int tid = threadIdx.x;
    int wid = tid >> 5, lane = tid & 31;
    int g = lane >> 2, t4 = lane & 3;
    int wm = wid & 1, wn = wid >> 1;
    int m0 = wm * 64, n0 = wn * 64;

    size_t bm = (size_t)blockIdx.y * 128;
    size_t bn = (size_t)blockIdx.x * 128;
    int z = blockIdx.x;

    const int NC = K >> 6;

    float acc[4][8][4];
    #pragma unroll
    for (int i = 0; i < 4; i++)
        #pragma unroll
        for (int j = 0; j < 8; j++)
            #pragma unroll
            for (int r = 0; r < 4; r++) acc[i][j][r] = 0.0f;

    int lr = lane & 7;
    uint32_t aoff = (uint32_t)((m0 + ((lane >> 3) & 1) * 8 + lr) * GRB + (lane >> 4) * 16);
    uint32_t boff = (uint32_t)(GB_OFF + (n0 + (lane >> 4) * 8 + lr) * GRB + ((lane >> 3) & 1) * 16);

    auto load_chunk = [&](int c, int st) {
        const __half* Ak = A + c * 64;
        const __half* Bk = B + c * 64;
        uint32_t sA = sbase + (uint32_t)st * GSTAGE_BYTES;
        #pragma unroll
        for (int i = 0; i < 8; i++) {
            int idx = tid + i * 128;
            int row = idx >> 3, seg = idx & 7;
            cpa16(sA + row * GRB + seg * 16, Ak + (bm + row) * (size_t)lda + seg * 8);
            cpa16(sA + GB_OFF + row * GRB + seg * 16, Bk + (bn + row) * (size_t)ldb + seg * 8);
        }
        asm volatile("cp.async.commit_group;" ::: "memory");
    };

    load_chunk(0, 0);

    for (int c = 0; c < NC; c++) {
        int st = c & 1;
        asm volatile("cp.async.wait_group 0;" ::: "memory");
        __syncthreads();

        if (c + 1 < NC) load_chunk(c + 1, st ^ 1);

        uint32_t sg = sbase + (uint32_t)st * GSTAGE_BYTES;

        #pragma unroll
        for (int ks = 0; ks < 4; ks++) {
            uint32_t a[4][4];
            #pragma unroll
            for (int mt = 0; mt < 4; mt++)
                LDMX4(a[mt], sg + aoff + mt * (16 * GRB) + ks * 32);
            #pragma unroll
            for (int np = 0; np < 4; np++) {
                uint32_t b[4];
                LDMX4(b, sg + boff + np * (16 * GRB) + ks * 32);
                #pragma unroll
                for (int mt = 0; mt < 4; mt++) {
                    MMA16816(acc[mt][np * 2],
                             a[mt][0], a[mt][1], a[mt][2], a[mt][3], b[0], b[1]);
                    MMA16816(acc[mt][np * 2 + 1],
                             a[mt][0], a[mt][1], a[mt][2], a[mt][3], b[2], b[3]);
                }
            }
        }
    }

    if (EPI == EPI_PLAIN) {
        #pragma unroll
        for (int mt = 0; mt < 4; mt++) {
            size_t row = bm + m0 + mt * 16 + g;
            #pragma unroll
            for (int nt = 0; nt < 8; nt++) {
                size_t col = bn + n0 + nt * 8 + 2 * t4;
                *(float2*)&C[row * (size_t)ldc + col] =
                    make_float2(acc[mt][nt][0], acc[mt][nt][1]);
                *(float2*)&C[(row + 8) * (size_t)ldc + col] =
                    make_float2(acc[mt][nt][2], acc[mt][nt][3]);
            }
        }
        return;
    }

    // ---------------- EPI_QKV ----------------
    if (z >= NH + NKV) {
        int kh = z - (NH + NKV);
        #pragma unroll
        for (int mt = 0; mt < 4; mt++) {
            size_t tok = bm + m0 + mt * 16 + g;
            int bb = (int)(tok >> 11);
            int s  = (int)(tok & (SEQ - 1));
            __half* d0 = vo + ((size_t)(bb * NKV + kh) * SEQ + s) * HD;
            __half* d1 = d0 + (size_t)8 * HD;
            #pragma unroll
            for (int nt = 0; nt < 8; nt++) {
                int cc = n0 + nt * 8 + 2 * t4;
                *(__half2*)&d0[cc] = __floats2half2_rn(acc[mt][nt][0], acc[mt][nt][1]);
                *(__half2*)&d1[cc] = __floats2half2_rn(acc[mt][nt][2], acc[mt][nt][3]);
            }
        }
        return;
    }

    __syncthreads();
    float* red = (float*)smc;             // [128][2]

    #pragma unroll
    for (int mt = 0; mt < 4; mt++) {
        float s0 = 0.0f, s1 = 0.0f;
        #pragma unroll
        for (int nt = 0; nt < 8; nt++) {
            s0 += acc[mt][nt][0] * acc[mt][nt][0] + acc[mt][nt][1] * acc[mt][nt][1];
            s1 += acc[mt][nt][2] * acc[mt][nt][2] + acc[mt][nt][3] * acc[mt][nt][3];
        }
        s0 += __shfl_xor_sync(0xFFFFFFFFu, s0, 1);
        s0 += __shfl_xor_sync(0xFFFFFFFFu, s0, 2);
        s1 += __shfl_xor_sync(0xFFFFFFFFu, s1, 1);
        s1 += __shfl_xor_sync(0xFFFFFFFFu, s1, 2);
        if (t4 == 0) {
            int r0 = m0 + mt * 16 + g;
            red[r0 * 2 + wn]       = s0;
            red[(r0 + 8) * 2 + wn] = s1;
        }
    }
    __syncthreads();

    const float* w = (z < NH) ? qw : kw;
    #pragma unroll
    for (int mt = 0; mt < 4; mt++) {
        int r0 = m0 + mt * 16 + g;
        float inv0 = rsqrtf((red[r0 * 2] + red[r0 * 2 + 1]) * (1.0f / HD) + 1e-5f);
        float inv1 = rsqrtf((red[(r0 + 8) * 2] + red[(r0 + 8) * 2 + 1]) * (1.0f / HD) + 1e-5f);
        size_t tok = bm + r0;
        int bb = (int)(tok >> 11);
        int s  = (int)(tok & (SEQ - 1));
        __half* d0;
        if (z < NH) d0 = qo + ((size_t)(bb * NH + z) * SEQ + s) * HD;
        else        d0 = ko + ((size_t)(bb * NKV + (z - NH)) * SEQ + s) * HD;
        __half* d1 = d0 + (size_t)8 * HD;
        const float* cr0 = cosb + (size_t)s * (HD / 2);
        const float* sr0 = sinb + (size_t)s * (HD / 2);
        const float* cr1 = cr0 + 8 * (HD / 2);
        const float* sr1 = sr0 + 8 * (HD / 2);
        #pragma unroll
        for (int nt = 0; nt < 8; nt++) {
            int cc = n0 + nt * 8 + 2 * t4;
            int ii = cc >> 1;
            float w0 = w[cc], w1 = w[cc + 1];
            float c0 = cr0[ii], sn0 = sr0[ii];
            float c1 = cr1[ii], sn1 = sr1[ii];
            float y0 = acc[mt][nt][0] * inv0 * w0;
            float y1 = acc[mt][nt][1] * inv0 * w1;
            float y2 = acc[mt][nt][2] * inv1 * w0;
            float y3 = acc[mt][nt][3] * inv1 * w1;
            *(__half2*)&d0[cc] = __floats2half2_rn(y0 * c0 - y1 * sn0, y0 * sn0 + y1 * c0);
            *(__half2*)&d1[cc] = __floats2half2_rn(y2 * c1 - y3 * sn1, y2 * sn1 + y3 * c1);
        }
    }
}

// ============================================================================
//  fused flash attention: 256 threads, 8 warps (4m x 2n), warp tile 32x64
// ============================================================================
#define FRB  272              // row bytes (128 halves + 8 pad)
#define FRU  68               // row u32
#define SM_Q   0
#define SM_P   34816
#define SM_KV  69632
#define KV_STG 69632          // K 34816 + V 34816
#define FSMEM_TOTAL (SM_KV + 2 * KV_STG)   // 208896 B
#define NKVB (SEQ / 128)      // 16

__global__ __launch_bounds__(256, 1)
void flash_attn(const __half* __restrict__ q, const __half* __restrict__ k,
                const __half* __restrict__ v, const int* __restrict__ mask,
                __half* __restrict__ att, float scale2)   // scale2 = scale * log2(e)
{
    extern __shared__ char smc[];
    uint32_t sbase = smem_u32(smc);

    int tid = threadIdx.x;
    int wid = tid >> 5, lane = tid & 31;
    int g = lane >> 2, t4 = lane & 3, lr = lane & 7;
    int wm = wid & 3, wn = wid >> 2;          // 4m x 2n
    int m0 = wm * 32, n0 = wn * 64;

    int z  = blockIdx.y;
    size_t bm = (size_t)blockIdx.x * 128;

    const __half* Qg = q + ((size_t)z * SEQ + bm) * HD;
    const __half* Kg = k + (size_t)(z >> 1) * SEQ * HD;
    const __half* Vg = v + (size_t)(z >> 1) * SEQ * HD;
    const int* mrow  = mask + (size_t)(z >> 4) * SEQ;

    uint32_t a_base  = (uint32_t)((m0 + ((lane >> 3) & 1) * 8 + lr) * FRB + (lane >> 4) * 16);
    uint32_t b_base  = (uint32_t)((n0 + (lane >> 4) * 8 + lr) * FRB + ((lane >> 3) & 1) * 16);
    uint32_t vb_base = (uint32_t)((((lane >> 3) & 1) * 8 + lr) * FRB + (n0 + (lane >> 4) * 8) * 2);

    float acc_o[2][8][4];
    #pragma unroll
    for (int i = 0; i < 2; i++)
        #pragma unroll
        for (int j = 0; j < 8; j++)
            #pragma unroll
            for (int r = 0; r < 4; r++) acc_o[i][j][r] = 0.0f;
    float rsum[2][2] = {};

    auto load_stage = [&](int c, int st) {
        uint32_t sK = sbase + SM_KV + (uint32_t)st * KV_STG;
        uint32_t sV = sK + 34816;
        #pragma unroll
        for (int i = 0; i < 8; i++) {
            int idx = tid + i * 256;
            int row = idx >> 4, seg = idx & 15;
            cpa16(sK + row * FRB + seg * 16, Kg + ((size_t)(c * 128 + row)) * HD + seg * 8);
            cpa16(sV + row * FRB + seg * 16, Vg + ((size_t)(c * 128 + row)) * HD + seg * 8);
        }
        asm volatile("cp.async.commit_group;" ::: "memory");
    };

    #pragma unroll
    for (int i = 0; i < 8; i++) {
        int idx = tid + i * 256;
        int row = idx >> 4, seg = idx & 15;
        cpa16(sbase + SM_Q + row * FRB + seg * 16, Qg + (size_t)row * HD + seg * 8);
    }
    load_stage(0, 0);

    for (int c = 0; c < NKVB; c++) {
        int st = c & 1;
        asm volatile("cp.async.wait_group 0;" ::: "memory");
        __syncthreads();

        if (c + 1 < NKVB) load_stage(c + 1, st ^ 1);

        uint32_t sQ = sbase + SM_Q;
        uint32_t sK = sbase + SM_KV + (uint32_t)st * KV_STG;
        uint32_t sV = sK + 34816;
        uint32_t sP = sbase + SM_P;

        // ---- S = Q @ K^T, warp tile 32q x 64kv ----
        float acc_s[2][8][4];
        #pragma unroll
        for (int i = 0; i < 2; i++)
            #pragma unroll
            for (int j = 0; j < 8; j++)
                #pragma unroll
                for (int r = 0; r < 4; r++) acc_s[i][j][r] = 0.0f;

        #pragma unroll
        for (int kt = 0; kt < 8; kt++) {
            uint32_t a[2][4];
            LDMX4(a[0], sQ + a_base + kt * 32);
            LDMX4(a[1], sQ + a_base + 16 * FRB + kt * 32);
            #pragma unroll
            for (int np = 0; np < 4; np++) {
                uint32_t b[4];
                LDMX4(b, sK + b_base + np * (16 * FRB) + kt * 32);
                #pragma unroll
                for (int mt = 0; mt < 2; mt++) {
                    MMA16816(acc_s[mt][np * 2],
                             a[mt][0], a[mt][1], a[mt][2], a[mt][3], b[0], b[1]);
                    MMA16816(acc_s[mt][np * 2 + 1],
                             a[mt][0], a[mt][1], a[mt][2], a[mt][3], b[2], b[3]);
                }
            }
        }

        // ---- exp2(s*scale2) * mask, rowsum accum, pack P ----
        uint32_t* Ps = (uint32_t*)(smc + SM_P);
        #pragma unroll
        for (int nb = 0; nb < 8; nb++) {
            int col0 = c * 128 + n0 + nb * 8 + 2 * t4;
            float mk0 = mrow[col0]     ? 1.0f : 0.0f;
            float mk1 = mrow[col0 + 1] ? 1.0f : 0.0f;
            #pragma unroll
            for (int mt = 0; mt < 2; mt++) {
                float e0 = ex2f(acc_s[mt][nb][0] * scale2) * mk0;
                float e1 = ex2f(acc_s[mt][nb][1] * scale2) * mk1;
                float e2 = ex2f(acc_s[mt][nb][2] * scale2) * mk0;
                float e3 = ex2f(acc_s[mt][nb][3] * scale2) * mk1;
                rsum[mt][0] += e0 + e1;
                rsum[mt][1] += e2 + e3;
                int prow = m0 + mt * 16 + g;
                int pcol = wn * 32 + nb * 4 + t4;
                __half2 h01 = __floats2half2_rn(e0, e1);
                __half2 h23 = __floats2half2_rn(e2, e3);
                Ps[prow * FRU + pcol]       = *(uint32_t*)&h01;
                Ps[(prow + 8) * FRU + pcol] = *(uint32_t*)&h23;
            }
        }
        __syncthreads();

        // ---- out += P @ V, warp tile 32q x 64hd (trans ldmatrix on V) ----
        #pragma unroll
        for (int kt = 0; kt < 8; kt++) {
            uint32_t a[2][4];
            LDMX4(a[0], sP + a_base + kt * 32);
            LDMX4(a[1], sP + a_base + 16 * FRB + kt * 32);
            #pragma unroll
            for (int np = 0; np < 4; np++) {
                uint32_t b[4];
                LDMX4T(b, sV + vb_base + kt * (16 * FRB) + np * 32);
                #pragma unroll
                for (int mt = 0; mt < 2; mt++) {
                    MMA16816(acc_o[mt][np * 2],
                             a[mt][0], a[mt][1], a[mt][2], a[mt][3], b[0], b[1]);
                    MMA16816(acc_o[mt][np * 2 + 1],
                             a[mt][0], a[mt][1], a[mt][2], a[mt][3], b[2], b[3]);
                }
            }
        }
    }

    // ---- rowsum reduce across 2 wn warps, divide, store ----
    __syncthreads();
    float* red = (float*)(smc + SM_P);   // [128][2]
    #pragma unroll
    for (int mt = 0; mt < 2; mt++) {
        #pragma unroll
        for (int h = 0; h < 2; h++) {
            float s = rsum[mt][h];
            s += __shfl_xor_sync(0xFFFFFFFFu, s, 1);
            s += __shfl_xor_sync(0xFFFFFFFFu, s, 2);
            rsum[mt][h] = s;
        }
    }
    if (t4 == 0) {
        #pragma unroll
        for (int mt = 0; mt < 2; mt++) {
            int r0 = m0 + mt * 16 + g;
            red[r0 * 2 + wn]       = rsum[mt][0];
            red[(r0 + 8) * 2 + wn] = rsum[mt][1];
        }
    }
    __syncthreads();

    int b = z >> 4, h = z & 15;
    #pragma unroll
    for (int mt = 0; mt < 2; mt++) {
        int r0 = m0 + mt * 16 + g;
        float t0 = red[r0 * 2] + red[r0 * 2 + 1];
        float t1 = red[(r0 + 8) * 2] + red[(r0 + 8) * 2 + 1];
        float i0 = (t0 > 0.0f) ? (1.0f / t0) : 0.0f;
        float i1 = (t1 > 0.0f) ? (1.0f / t1) : 0.0f;
        size_t s0 = bm + r0;
        __half* d0 = att + ((size_t)b * SEQ + s0) * DIM + h * HD;
        __half* d1 = att + ((size_t)b * SEQ + s0 + 8) * DIM + h * HD;
        #pragma unroll
        for (int nt = 0; nt < 8; nt++) {
            int col = n0 + nt * 8 + 2 * t4;
            *(__half2*)&d0[col] = __floats2half2_rn(acc_o[mt][nt][0] * i0, acc_o[mt][nt][1] * i0);
            *(__half2*)&d1[col] = __floats2half2_rn(acc_o[mt][nt][2] * i1, acc_o[mt][nt][3] * i1);
        }
    }
}

// ---------------- merged fp32 -> fp16 conversion (3 tensors, 1 launch) ----------------
__global__ __launch_bounds__(256)
void tohalf3(const float2* __restrict__ s0, __half2* __restrict__ d0, int n0,
             const float2* __restrict__ s1, __half2* __restrict__ d1, int n1,
             const float2* __restrict__ s2, __half2* __restrict__ d2, int n2)
{
    int total = n0 + n1 + n2;
    int i = blockIdx.x * 256 + threadIdx.x;
    int stride = gridDim.x * 256;
    for (; i < total; i += stride) {
        const float2* s; __half2* d; int j = i;
        if (j < n0)            { s = s0; d = d0; }
        else if (j < n0 + n1)  { s = s1; d = d1; j -= n0; }
        else                   { s = s2; d = d2; j -= n0 + n1; }
        float2 v = s[j];
        d[j] = __floats2half2_rn(v.x, v.y);
    }
}

// ---------------- launch ----------------
extern "C" void kernel_launch(void* const* d_in, const int* in_sizes, int n_in,
                              void* d_out, int out_size)
{
    const float* x     = (const float*)d_in[0];
    const int*   xmask = (const int*)  d_in[1];
    const float* fcos  = (const float*)d_in[2];
    const float* fsin  = (const float*)d_in[3];
    const float* Wqkv  = (const float*)d_in[4];
    const float* Wout  = (const float*)d_in[5];
    const float* qw    = (const float*)d_in[6];
    const float* kw    = (const float*)d_in[7];
    float* out = (float*)d_out;

    __half *q, *k, *v, *att, *xh, *wq, *wo;
    cudaGetSymbolAddress((void**)&q,   g_q);
    cudaGetSymbolAddress((void**)&k,   g_k);
    cudaGetSymbolAddress((void**)&v,   g_v);
    cudaGetSymbolAddress((void**)&att, g_att);
    cudaGetSymbolAddress((void**)&xh,  g_xh);
    cudaGetSymbolAddress((void**)&wq,  g_wq);
    cudaGetSymbolAddress((void**)&wo,  g_wo);

    cudaFuncSetAttribute(mma_gemm<EPI_PLAIN>, cudaFuncAttributeMaxDynamicSharedMemorySize, GSMEM_TOTAL);
    cudaFuncSetAttribute(mma_gemm<EPI_QKV>,   cudaFuncAttributeMaxDynamicSharedMemorySize, GSMEM_TOTAL);
    cudaFuncSetAttribute(flash_attn, cudaFuncAttributeMaxDynamicSharedMemorySize, FSMEM_TOTAL);

    float scale2 = rsqrtf((float)HD) * 1.4426950408889634f;   // scale * log2(e)

    // 0) convert raw GEMM inputs to fp16 (single launch)
    tohalf3<<<2368, 256>>>(
        (const float2*)x,    (__half2*)xh, (NTOK * DIM) / 2,
        (const float2*)Wqkv, (__half2*)wq, (QKVD * DIM) / 2,
        (const float2*)Wout, (__half2*)wo, (DIM * DIM) / 2);

    // 1) fused QKV GEMM + RMSNorm + RoPE -> g_q / g_k / g_v (fp16)
    mma_gemm<EPI_QKV><<<dim3(QKVD / 128, NTOK / 128), 128, GSMEM_TOTAL>>>(
        xh, wq, nullptr, DIM, DIM, DIM, 0, fcos, fsin, qw, kw, q, k, v);

    // 2) fused attention -> att (fp16)
    flash_attn<<<dim3(SEQ / 128, BSZ * NH), 256, FSMEM_TOTAL>>>(
        q, k, v, xmask, att, scale2);

    // 3) out = att @ Wout^T (fp32)
    mma_gemm<EPI_PLAIN><<<dim3(DIM / 128, NTOK / 128), 128, GSMEM_TOTAL>>>(
        att, wo, out, DIM, DIM, DIM, DIM,
        nullptr, nullptr, nullptr, nullptr, nullptr, nullptr, nullptr);
}